// round 13
// baseline (speedup 1.0000x reference)
#include <cuda_runtime.h>
#include <math.h>

#define NN 16384
#define EE 262144
typedef unsigned long long ull;
typedef unsigned int u32;

__device__ float g_ns  [NN * 120];
__device__ float g_ne  [NN * 240];
__device__ float g_qinv[NN * 120];
__device__ float g_kinv[NN * 120];
__device__ float g_vinv[NN * 120];
__device__ float g_qsph[NN * 120];
__device__ float g_ksph[NN * 120];
__device__ float g_vsph[NN * 112];
__device__ float g_w   [(size_t)EE * 120];
// fragment-layout tf32 weights, 15360 words per weight:
// wid 0=inv_w1 1=rbf_w1 2=inv_w2 3=rbf_w2 4=Wq 5=Wk 6=Wv 7=Wqs 8=Wks 9=Wvs
__device__ u32 g_wfrag[10*15360];

__device__ __forceinline__ float4 ldg4(const float* p){ return __ldg(reinterpret_cast<const float4*>(p)); }
__device__ __forceinline__ void red4(float* p, float a, float b, float c, float d){
    asm volatile("red.global.add.v4.f32 [%0],{%1,%2,%3,%4};"::"l"(p),"f"(a),"f"(b),"f"(c),"f"(d):"memory");
}
__device__ __forceinline__ float wsum(float v){
    #pragma unroll
    for (int o=16;o;o>>=1) v += __shfl_xor_sync(0xffffffffu, v, o);
    return v;
}
__device__ __forceinline__ u32 f2tf32(float v){
    u32 t; asm("cvt.rna.tf32.f32 %0, %1;" : "=r"(t) : "f"(v)); return t;
}
__device__ __forceinline__ void mma_tf32(float* c, u32 a0,u32 a1,u32 a2,u32 a3, u32 b0,u32 b1){
    asm volatile("mma.sync.aligned.m16n8k8.row.col.f32.tf32.tf32.f32 "
        "{%0,%1,%2,%3},{%4,%5,%6,%7},{%8,%9},{%0,%1,%2,%3};"
        : "+f"(c[0]),"+f"(c[1]),"+f"(c[2]),"+f"(c[3])
        : "r"(a0),"r"(a1),"r"(a2),"r"(a3),"r"(b0),"r"(b1));
}

// A-frag (64 rows x 8k per ktile): ((kt*4+mti)*32+lane)*4 + r
__device__ __forceinline__ void st_af(float* base, int row, int k, float v){
    int kt=k>>3, mti=row>>4, rm=row&15, kc=k&7;
    int r = ((rm>>3)&1) + ((kc>>2)<<1);
    int lane = (rm&7)*4 + (kc&3);
    reinterpret_cast<u32*>(base)[((kt*4+mti)*32+lane)*4 + r] = f2tf32(v);
}
// paired store: (row,col) and (row+8,col), requires (row&15)<8 -> STS.64
__device__ __forceinline__ void st_af2(float* base, int row, int col, float vlo, float vhi){
    int kt=col>>3, mti=row>>4, rm=row&15, kc=col&7;
    int r = (kc>>2)<<1;
    int lane = (rm&7)*4 + (kc&3);
    uint2* p = reinterpret_cast<uint2*>(reinterpret_cast<u32*>(base) + ((kt*4+mti)*32+lane)*4 + r);
    *p = make_uint2(f2tf32(vlo), f2tf32(vhi));
}

// one k-step over warp's 32x32 tile; B fragments from gmem (L2)
__device__ __forceinline__ void mma_step(const float* af, const u32* __restrict__ bw,
                                         int kt, int wm, int lane, float acc[2][4][4]){
    u32 a[2][4], b[4][2];
    #pragma unroll
    for (int nt=0; nt<4; nt++){
        uint2 v = __ldg(reinterpret_cast<const uint2*>(bw + kt*1024 + nt*64));
        b[nt][0]=v.x; b[nt][1]=v.y;
    }
    #pragma unroll
    for (int mt=0; mt<2; mt++){
        float4 v = *reinterpret_cast<const float4*>(af + ((size_t)((kt*4 + wm*2+mt)*32+lane))*4);
        a[mt][0]=__float_as_uint(v.x); a[mt][1]=__float_as_uint(v.y);
        a[mt][2]=__float_as_uint(v.z); a[mt][3]=__float_as_uint(v.w);
    }
    #pragma unroll
    for (int mt=0; mt<2; mt++){
        #pragma unroll
        for (int nt=0; nt<4; nt++)
            mma_tf32(acc[mt][nt], a[mt][0],a[mt][1],a[mt][2],a[mt][3], b[nt][0],b[nt][1]);
    }
}

__device__ __forceinline__ void zero_acc(float acc[2][4][4]){
    #pragma unroll
    for (int i=0;i<2;i++){
        #pragma unroll
        for (int j=0;j<4;j++){
            #pragma unroll
            for (int r=0;r<4;r++) acc[i][j][r]=0.f;
        }
    }
}
__device__ __forceinline__ float silu(float x){ return x/(1.f+__expf(-x)); }

// silu(acc + sb[col]) -> A-frag store (vectorized STS.64 pairs)
__device__ __forceinline__ void epilogue_h(float acc[2][4][4], const float* sb, float* hbase,
                                           int wm, int wn, int lane){
    int r0 = wm*32 + (lane>>2);
    int c0b = wn*32 + 2*(lane&3);
    #pragma unroll
    for (int mt=0; mt<2; mt++){
        int row0 = r0 + mt*16;
        #pragma unroll
        for (int nt=0; nt<4; nt++){
            int col0 = c0b + nt*8;
            if (col0 < 120){
                float b0 = sb[col0], b1 = sb[col0+1];
                st_af2(hbase, row0, col0,   silu(acc[mt][nt][0]+b0), silu(acc[mt][nt][2]+b0));
                st_af2(hbase, row0, col0+1, silu(acc[mt][nt][1]+b1), silu(acc[mt][nt][3]+b1));
            }
        }
    }
}

// ---------- setup: convert all 10 weights to fragment-layout tf32 ----------
__global__ void conv_weights_kernel(
    const float* __restrict__ w0, const float* __restrict__ w1,
    const float* __restrict__ w2, const float* __restrict__ w3,
    const float* __restrict__ w4, const float* __restrict__ w5,
    const float* __restrict__ w6, const float* __restrict__ w7,
    const float* __restrict__ w8, const float* __restrict__ w9)
{
    int wid = blockIdx.y;
    int l = blockIdx.x*256 + threadIdx.x;
    if (l >= 15360) return;
    const int nktA[10] = {14,3,15,15,15,15,15,15,15,15};
    const int KA[10]   = {112,20,120,120,120,120,120,120,120,120};
    int kt = l>>10;
    if (kt >= nktA[wid]) return;
    const float* W = (wid==0)?w0:(wid==1)?w1:(wid==2)?w2:(wid==3)?w3:(wid==4)?w4:
                     (wid==5)?w5:(wid==6)?w6:(wid==7)?w7:(wid==8)?w8:w9;
    int ld = (wid==9)?112:120;
    int N  = (wid==9)?112:120;
    int K  = KA[wid];
    int rest = l&1023;
    int nti = rest>>6, lane=(rest>>1)&31, r = rest&1;
    int n = nti*8 + (lane>>2);
    int k = kt*8 + (lane&3) + 4*r;
    float v = (n<N && k<K) ? __ldg(W + (size_t)k*ld + n) : 0.f;
    g_wfrag[wid*15360 + l] = f2tf32(v);
}

// ---------- K1: node LayerNorm + O3 LayerNorm + residual copy to out ----------
__global__ void node_norm_kernel(const float* __restrict__ xs_in, const float* __restrict__ xe_in,
                                 const float* __restrict__ lnw, const float* __restrict__ lnb,
                                 const float* __restrict__ o3w, float* __restrict__ out){
    int lane = threadIdx.x & 31;
    int node = blockIdx.x*4 + (threadIdx.x >> 5);
    if (node >= NN) return;
    float* outS = out + (size_t)node*120;
    float* outE = out + (size_t)NN*120 + (size_t)node*240;

    const float* xs = xs_in + (size_t)node*120;
    float v0=xs[lane], v1=xs[lane+32], v2=xs[lane+64], v3=(lane<24)?xs[lane+96]:0.f;
    outS[lane]=v0; outS[lane+32]=v1; outS[lane+64]=v2;
    if (lane<24) outS[lane+96]=v3;
    float s = wsum(v0+v1+v2+v3);
    float q = wsum(v0*v0+v1*v1+v2*v2+v3*v3);
    float mean = s*(1.f/120.f);
    float inv = rsqrtf(q*(1.f/120.f) - mean*mean + 1e-5f);
    float* ns = g_ns + (size_t)node*120;
    ns[lane]    = (v0-mean)*inv*__ldg(lnw+lane)    + __ldg(lnb+lane);
    ns[lane+32] = (v1-mean)*inv*__ldg(lnw+lane+32) + __ldg(lnb+lane+32);
    ns[lane+64] = (v2-mean)*inv*__ldg(lnw+lane+64) + __ldg(lnb+lane+64);
    if (lane<24) ns[lane+96] = (v3-mean)*inv*__ldg(lnw+lane+96) + __ldg(lnb+lane+96);

    const float* xe = xe_in + (size_t)node*240;
    float* ne = g_ne + (size_t)node*240;
    {
        float e0=xe[lane], e1=xe[lane+32];
        outE[lane]=e0; outE[lane+32]=e1;
        float m = wsum(e0+e1)*(1.f/64.f);
        float c0=e0-m, c1=e1-m;
        float r = rsqrtf(wsum(c0*c0+c1*c1)*(1.f/64.f) + 1e-5f);
        ne[lane]    = c0*r*__ldg(o3w+lane);
        ne[lane+32] = c1*r*__ldg(o3w+lane+32);
    }
    {
        float y0=xe[64+lane], y1=xe[96+lane], y2=xe[128+lane];
        outE[64+lane]=y0; outE[96+lane]=y1; outE[128+lane]=y2;
        float r = rsqrtf(wsum(y0*y0+y1*y1+y2*y2)*(1.f/96.f) + 1e-5f);
        ne[64+lane]  = y0*r*__ldg(o3w+64+(lane)/3);
        ne[96+lane]  = y1*r*__ldg(o3w+64+(32+lane)/3);
        ne[128+lane] = y2*r*__ldg(o3w+64+(64+lane)/3);
    }
    {
        float z0=xe[160+lane], z1=xe[192+lane], z2=(lane<16)?xe[224+lane]:0.f;
        outE[160+lane]=z0; outE[192+lane]=z1;
        if (lane<16) outE[224+lane]=z2;
        float r = rsqrtf(wsum(z0*z0+z1*z1+z2*z2)*(1.f/80.f) + 1e-5f);
        ne[160+lane] = z0*r*__ldg(o3w+96+(lane)/5);
        ne[192+lane] = z1*r*__ldg(o3w+96+(32+lane)/5);
        if (lane<16) ne[224+lane] = z2*r*__ldg(o3w+96+(64+lane)/5);
    }
}

// ---------- K2: all 6 projections via mma.sync, A staged once ----------
__global__ __launch_bounds__(256,3) void proj_mma_kernel(void){
    __shared__ alignas(16) float af[15*512];
    int tid = threadIdx.x;
    int warp = tid>>5, lane = tid&31;
    int wm = warp>>2, wn = warp&3;
    int row0 = blockIdx.x * 64;

    for (int idx=tid; idx<64*30; idx+=256){
        int row = idx/30, q = idx - row*30;
        float4 v = ldg4(g_ns + (size_t)(row0+row)*120 + 4*q);
        st_af(af, row, 4*q,   v.x);
        st_af(af, row, 4*q+1, v.y);
        st_af(af, row, 4*q+2, v.z);
        st_af(af, row, 4*q+3, v.w);
    }
    __syncthreads();

    int boff = (wn*4)*64 + lane*2;
    int r0 = wm*32 + (lane>>2);
    int c0b = wn*32 + 2*(lane&3);

    #pragma unroll
    for (int sel=0; sel<6; sel++){
        const u32* bw = g_wfrag + (4+sel)*15360 + boff;
        float* C = (sel==0)?g_qinv:(sel==1)?g_kinv:(sel==2)?g_vinv:(sel==3)?g_qsph:(sel==4)?g_ksph:g_vsph;
        int ncols = (sel==5)?112:120;
        float acc[2][4][4];
        zero_acc(acc);
        #pragma unroll
        for (int kt=0; kt<15; kt++) mma_step(af, bw, kt, wm, lane, acc);
        #pragma unroll
        for (int mt=0; mt<2; mt++){
            int rowA = r0 + mt*16;
            #pragma unroll
            for (int nt=0; nt<4; nt++){
                int col0 = c0b + nt*8;
                if (col0 < ncols){
                    *reinterpret_cast<float2*>(C + (size_t)(row0+rowA)*ncols   + col0) =
                        make_float2(acc[mt][nt][0], acc[mt][nt][1]);
                    *reinterpret_cast<float2*>(C + (size_t)(row0+rowA+8)*ncols + col0) =
                        make_float2(acc[mt][nt][2], acc[mt][nt][3]);
                }
            }
        }
    }
}

// ---------- fused edge kernel: 64-edge tiles, coalesced gather, B frags from L2 ----------
#define AF1X 0
#define AF2X 7680
#define AFRX 15360
#define XSB1 16896
#define XSB2 17024
#define XSB3 17152
#define XFC  17280
#define EM_FLOATS 17344

__global__ __launch_bounds__(256,3) void edge_mma_kernel(
    const int* __restrict__ ei, const float* __restrict__ rbf, const float* __restrict__ fcut,
    const float* __restrict__ inv_b1, const float* __restrict__ inv_b2,
    const float* __restrict__ rbf_b1, const float* __restrict__ rbf_b2)
{
    extern __shared__ float sm[];
    int tid = threadIdx.x;
    int warp = tid>>5, lane = tid&31;
    int wm = warp>>2, wn = warp&3;
    int e0 = blockIdx.x * 64;

    int boff = (wn*4)*64 + lane*2;
    const u32* bw1  = g_wfrag + 0*15360 + boff;
    const u32* bwr1 = g_wfrag + 1*15360 + boff;
    const u32* bw2  = g_wfrag + 2*15360 + boff;
    const u32* bwr2 = g_wfrag + 3*15360 + boff;

    // zero rbf A-frag pad (kt=2, regs 2..3)
    for (int idx=tid; idx<256; idx+=256){
        int mti = idx>>6, rest = idx&63, ln = rest>>1, r = 2+(rest&1);
        sm[AFRX + ((2*4+mti)*32+ln)*4 + r] = 0.f;
    }
    if (tid < 128){
        sm[XSB1+tid] = (tid<120) ? __ldg(inv_b1+tid) : 0.f;
        sm[XSB2+tid] = (tid<120) ? __ldg(rbf_b1+tid) : 0.f;
        sm[XSB3+tid] = (tid<120) ? (__ldg(inv_b2+tid)+__ldg(rbf_b2+tid)) : 0.f;
    }
    if (tid < 64) sm[XFC+tid] = __ldg(fcut + e0 + tid);

    // gather + equi_dot: coalesced float4 loads; l=0 direct from regs; l>=1 via scratch
    {
        float* scr = sm + AF2X + warp*256;   // comps 64..239 used
        for (int el = warp; el < 64; el += 8){
            int e = e0 + el;
            int a_n = __ldg(ei+EE+e), b_n = __ldg(ei+e);
            const float* a = g_ne + (size_t)a_n*240;
            const float* b = g_ne + (size_t)b_n*240;
            #pragma unroll
            for (int i=0; i<2; i++){
                int q = lane + 32*i;
                if (q < 60){
                    float4 av = ldg4(a + 4*q), bv = ldg4(b + 4*q);
                    float dx=av.x-bv.x, dy=av.y-bv.y, dz=av.z-bv.z, dw=av.w-bv.w;
                    float4 d2 = make_float4(dx*dx, dy*dy, dz*dz, dw*dw);
                    if (q < 16){
                        st_af(sm+AF1X, el, 4*q,   d2.x);
                        st_af(sm+AF1X, el, 4*q+1, d2.y);
                        st_af(sm+AF1X, el, 4*q+2, d2.z);
                        st_af(sm+AF1X, el, 4*q+3, d2.w);
                    } else {
                        *reinterpret_cast<float4*>(scr + 4*q) = d2;
                    }
                }
            }
            __syncwarp();
            { int bb = 64 + lane*3;
              st_af(sm+AF1X, el, 64+lane, scr[bb]+scr[bb+1]+scr[bb+2]); }
            if (lane<16){ int bb = 160 + lane*5;
              st_af(sm+AF1X, el, 96+lane, scr[bb]+scr[bb+1]+scr[bb+2]+scr[bb+3]+scr[bb+4]); }
            __syncwarp();
        }
    }
    for (int idx=tid; idx<64*20; idx+=256){
        int row = idx/20, k = idx - row*20;
        st_af(sm+AFRX, row, k, __ldg(rbf + (size_t)(e0+row)*20 + k));
    }
    __syncthreads();

    float acc[2][4][4];
    zero_acc(acc);

    // GEMM2: rbf @ rbf_w1
    #pragma unroll
    for (int kt=0; kt<3; kt++) mma_step(sm+AFRX, bwr1, kt, wm, lane, acc);
    __syncthreads();   // scratch reads done before h2 overwrites AF2
    epilogue_h(acc, sm+XSB2, sm+AF2X, wm, wn, lane);
    zero_acc(acc);

    // GEMM1: d @ inv_w1
    #pragma unroll
    for (int kt=0; kt<14; kt++) mma_step(sm+AF1X, bw1, kt, wm, lane, acc);
    __syncthreads();
    epilogue_h(acc, sm+XSB1, sm+AF1X, wm, wn, lane);
    zero_acc(acc);
    __syncthreads();

    // GEMM3: h1 @ inv_w2 + h2 @ rbf_w2
    #pragma unroll
    for (int kt=0; kt<15; kt++) mma_step(sm+AF1X, bw2,  kt, wm, lane, acc);
    #pragma unroll
    for (int kt=0; kt<15; kt++) mma_step(sm+AF2X, bwr2, kt, wm, lane, acc);

    // w = (acc + b) * fcut -> g_w
    {
        int r0 = wm*32 + (lane>>2);
        int c0b = wn*32 + 2*(lane&3);
        #pragma unroll
        for (int mt=0; mt<2; mt++){
            int rowA = r0 + mt*16;
            float fA = sm[XFC+rowA], fB = sm[XFC+rowA+8];
            #pragma unroll
            for (int nt=0; nt<4; nt++){
                int col0 = c0b + nt*8;
                if (col0 < 120){
                    float2 va, vb;
                    va.x = (acc[mt][nt][0] + sm[XSB3+col0])  *fA;
                    va.y = (acc[mt][nt][1] + sm[XSB3+col0+1])*fA;
                    vb.x = (acc[mt][nt][2] + sm[XSB3+col0])  *fB;
                    vb.y = (acc[mt][nt][3] + sm[XSB3+col0+1])*fB;
                    *reinterpret_cast<float2*>(g_w + (size_t)(e0+rowA)*120   + col0) = va;
                    *reinterpret_cast<float2*>(g_w + (size_t)(e0+rowA+8)*120 + col0) = vb;
                }
            }
        }
    }
}

// ---------- K6: attention + gated messages + scatter ----------
__global__ __launch_bounds__(256) void edge_attn_kernel(const int* __restrict__ ei,
                                                        const float* __restrict__ fcut,
                                                        const float* __restrict__ rsh,
                                                        float* __restrict__ outS,
                                                        float* __restrict__ outE){
    __shared__ float sgate[8][116];
    int warp = threadIdx.x>>5, lane = threadIdx.x&31;
    int e = blockIdx.x*8 + warp;
    int ct = __ldg(ei+e), nb = __ldg(ei+EE+e);
    float fc = __ldg(fcut+e);
    const float* w  = g_w   + (size_t)e*120;
    const float* qi = g_qinv + (size_t)ct*120;
    const float* ki = g_kinv + (size_t)nb*120;
    const float* vi = g_vinv + (size_t)nb*120;
    const float* qs = g_qsph + (size_t)ct*120;
    const float* ks = g_ksph + (size_t)nb*120;
    const float* vs = g_vsph + (size_t)nb*112;

    float s0=0,s1=0,s2=0,s3=0,t0=0,t1=0,t2=0;
    if (lane < 30){
        float4 wv = ldg4(w + 4*lane);
        float4 q  = ldg4(qi + 4*lane), k = ldg4(ki + 4*lane);
        float4 qe = ldg4(qs + 4*lane), ke = ldg4(ks + 4*lane);
        float wa[4]={wv.x,wv.y,wv.z,wv.w};
        float pa[4]={q.x*k.x, q.y*k.y, q.z*k.z, q.w*k.w};
        float pe[4]={qe.x*ke.x, qe.y*ke.y, qe.z*ke.z, qe.w*ke.w};
        #pragma unroll
        for (int j=0;j<4;j++){
            int idx = 4*lane + j;
            float p = wa[j]*pa[j];
            float pq = wa[j]*pe[j];
            int h = idx/30, l = idx/40;
            s0 += (h==0)?p:0.f; s1 += (h==1)?p:0.f; s2 += (h==2)?p:0.f; s3 += (h==3)?p:0.f;
            t0 += (l==0)?pq:0.f; t1 += (l==1)?pq:0.f; t2 += (l==2)?pq:0.f;
        }
    }
    const float SC_S = 0.091287092917527686f;
    const float SC_E = 0.094491118252306805f;
    s0 = wsum(s0)*SC_S; s1 = wsum(s1)*SC_S; s2 = wsum(s2)*SC_S; s3 = wsum(s3)*SC_S;
    t0 = wsum(t0)*SC_E; t1 = wsum(t1)*SC_E; t2 = wsum(t2)*SC_E;

    if (lane < 30){
        float4 v = ldg4(vi + 4*lane);
        float va[4]={v.x,v.y,v.z,v.w}, m[4];
        #pragma unroll
        for (int j=0;j<4;j++){
            int h = (4*lane+j)/30;
            float ss = (h==0)?s0:((h==1)?s1:((h==2)?s2:s3));
            m[j] = ss*va[j];
        }
        red4(outS + (size_t)ct*120 + 4*lane, m[0],m[1],m[2],m[3]);
    }
    if (lane < 28){
        float4 v = ldg4(vs + 4*lane);
        float va[4]={v.x,v.y,v.z,v.w};
        #pragma unroll
        for (int j=0;j<4;j++){
            int ir = 4*lane + j;
            float tl = (ir<64)?t0:((ir<96)?t1:t2);
            sgate[warp][ir] = tl*va[j]*fc;
        }
    }
    __syncwarp();
    if (lane < 30){
        int base = 8*lane;
        float4 r0 = ldg4(rsh + (size_t)e*240 + base);
        float4 r1 = ldg4(rsh + (size_t)e*240 + base + 4);
        float ra[8]={r0.x,r0.y,r0.z,r0.w,r1.x,r1.y,r1.z,r1.w}, m[8];
        #pragma unroll
        for (int j=0;j<8;j++){
            int c = base + j;
            int ir = (c<64)? c : (c<160)? 64+(c-64)/3 : 96+(c-160)/5;
            m[j] = ra[j]*sgate[warp][ir];
        }
        red4(outE + (size_t)ct*240 + base,     m[0],m[1],m[2],m[3]);
        red4(outE + (size_t)ct*240 + base + 4, m[4],m[5],m[6],m[7]);
    }
}

extern "C" void kernel_launch(void* const* d_in, const int* in_sizes, int n_in,
                              void* d_out, int out_size){
    const float* node_scalar=(const float*)d_in[0];
    const float* node_equi  =(const float*)d_in[1];
    const float* rbf        =(const float*)d_in[2];
    const float* fcut       =(const float*)d_in[3];
    const float* rsh        =(const float*)d_in[4];
    const float* ln_w =(const float*)d_in[5];
    const float* ln_b =(const float*)d_in[6];
    const float* o3w  =(const float*)d_in[7];
    const float* Wq   =(const float*)d_in[8];
    const float* Wk   =(const float*)d_in[9];
    const float* Wv   =(const float*)d_in[10];
    const float* Wqs  =(const float*)d_in[11];
    const float* Wks  =(const float*)d_in[12];
    const float* Wvs  =(const float*)d_in[13];
    const float* rbf_w1=(const float*)d_in[14];
    const float* rbf_b1=(const float*)d_in[15];
    const float* rbf_w2=(const float*)d_in[16];
    const float* rbf_b2=(const float*)d_in[17];
    const float* inv_w1=(const float*)d_in[18];
    const float* inv_b1=(const float*)d_in[19];
    const float* inv_w2=(const float*)d_in[20];
    const float* inv_b2=(const float*)d_in[21];
    const int*   ei    =(const int*)d_in[22];

    float* outS = (float*)d_out;
    float* outE = outS + (size_t)NN*120;

    cudaFuncSetAttribute(edge_mma_kernel, cudaFuncAttributeMaxDynamicSharedMemorySize, EM_FLOATS*4);

    conv_weights_kernel<<<dim3(60,10), 256>>>(inv_w1, rbf_w1, inv_w2, rbf_w2,
                                              Wq, Wk, Wv, Wqs, Wks, Wvs);
    node_norm_kernel<<<NN/4, 128>>>(node_scalar, node_equi, ln_w, ln_b, o3w, (float*)d_out);
    proj_mma_kernel<<<NN/64, 256>>>();
    edge_mma_kernel<<<EE/64, 256, EM_FLOATS*4>>>(ei, rbf, fcut, inv_b1, inv_b2, rbf_b1, rbf_b2);
    edge_attn_kernel<<<EE/8, 256>>>(ei, fcut, rsh, outS, outE);
}

// round 14
// speedup vs baseline: 1.0401x; 1.0401x over previous
#include <cuda_runtime.h>
#include <math.h>

#define NN 16384
#define EE 262144
typedef unsigned long long ull;
typedef unsigned int u32;

__device__ float g_ns  [NN * 120];
__device__ float g_ne  [NN * 240];
__device__ float g_qinv[NN * 120];
__device__ float g_kinv[NN * 120];
__device__ float g_vinv[NN * 120];
__device__ float g_qsph[NN * 120];
__device__ float g_ksph[NN * 120];
__device__ float g_vsph[NN * 112];
__device__ float g_w   [(size_t)EE * 120];
// fragment-layout tf32 weights, 15360 words per weight:
// wid 0=inv_w1 1=rbf_w1 2=inv_w2 3=rbf_w2 4=Wq 5=Wk 6=Wv 7=Wqs 8=Wks 9=Wvs
__device__ u32 g_wfrag[10*15360];

__device__ __forceinline__ float4 ldg4(const float* p){ return __ldg(reinterpret_cast<const float4*>(p)); }
__device__ __forceinline__ void red4(float* p, float a, float b, float c, float d){
    asm volatile("red.global.add.v4.f32 [%0],{%1,%2,%3,%4};"::"l"(p),"f"(a),"f"(b),"f"(c),"f"(d):"memory");
}
__device__ __forceinline__ float wsum(float v){
    #pragma unroll
    for (int o=16;o;o>>=1) v += __shfl_xor_sync(0xffffffffu, v, o);
    return v;
}
__device__ __forceinline__ u32 f2tf32(float v){
    u32 t; asm("cvt.rna.tf32.f32 %0, %1;" : "=r"(t) : "f"(v)); return t;
}
__device__ __forceinline__ void mma_tf32(float* c, u32 a0,u32 a1,u32 a2,u32 a3, u32 b0,u32 b1){
    asm volatile("mma.sync.aligned.m16n8k8.row.col.f32.tf32.tf32.f32 "
        "{%0,%1,%2,%3},{%4,%5,%6,%7},{%8,%9},{%0,%1,%2,%3};"
        : "+f"(c[0]),"+f"(c[1]),"+f"(c[2]),"+f"(c[3])
        : "r"(a0),"r"(a1),"r"(a2),"r"(a3),"r"(b0),"r"(b1));
}

// A-frag (64 rows x 8k per ktile): ((kt*4+mti)*32+lane)*4 + r
__device__ __forceinline__ void st_af(float* base, int row, int k, float v){
    int kt=k>>3, mti=row>>4, rm=row&15, kc=k&7;
    int r = ((rm>>3)&1) + ((kc>>2)<<1);
    int lane = (rm&7)*4 + (kc&3);
    reinterpret_cast<u32*>(base)[((kt*4+mti)*32+lane)*4 + r] = f2tf32(v);
}
// paired store: (row,col) and (row+8,col), requires (row&15)<8 -> STS.64
__device__ __forceinline__ void st_af2(float* base, int row, int col, float vlo, float vhi){
    int kt=col>>3, mti=row>>4, rm=row&15, kc=col&7;
    int r = (kc>>2)<<1;
    int lane = (rm&7)*4 + (kc&3);
    uint2* p = reinterpret_cast<uint2*>(reinterpret_cast<u32*>(base) + ((kt*4+mti)*32+lane)*4 + r);
    *p = make_uint2(f2tf32(vlo), f2tf32(vhi));
}

// one k-step over warp's 32x32 tile; B fragments from gmem (L2)
__device__ __forceinline__ void mma_step(const float* af, const u32* __restrict__ bw,
                                         int kt, int wm, int lane, float acc[2][4][4]){
    u32 a[2][4], b[4][2];
    #pragma unroll
    for (int nt=0; nt<4; nt++){
        uint2 v = __ldg(reinterpret_cast<const uint2*>(bw + kt*1024 + nt*64));
        b[nt][0]=v.x; b[nt][1]=v.y;
    }
    #pragma unroll
    for (int mt=0; mt<2; mt++){
        float4 v = *reinterpret_cast<const float4*>(af + ((size_t)((kt*4 + wm*2+mt)*32+lane))*4);
        a[mt][0]=__float_as_uint(v.x); a[mt][1]=__float_as_uint(v.y);
        a[mt][2]=__float_as_uint(v.z); a[mt][3]=__float_as_uint(v.w);
    }
    #pragma unroll
    for (int mt=0; mt<2; mt++){
        #pragma unroll
        for (int nt=0; nt<4; nt++)
            mma_tf32(acc[mt][nt], a[mt][0],a[mt][1],a[mt][2],a[mt][3], b[nt][0],b[nt][1]);
    }
}

__device__ __forceinline__ void zero_acc(float acc[2][4][4]){
    #pragma unroll
    for (int i=0;i<2;i++){
        #pragma unroll
        for (int j=0;j<4;j++){
            #pragma unroll
            for (int r=0;r<4;r++) acc[i][j][r]=0.f;
        }
    }
}
__device__ __forceinline__ float silu(float x){ return x/(1.f+__expf(-x)); }

// silu(acc + sb[col]) -> A-frag store (vectorized STS.64 pairs)
__device__ __forceinline__ void epilogue_h(float acc[2][4][4], const float* sb, float* hbase,
                                           int wm, int wn, int lane){
    int r0 = wm*32 + (lane>>2);
    int c0b = wn*32 + 2*(lane&3);
    #pragma unroll
    for (int mt=0; mt<2; mt++){
        int row0 = r0 + mt*16;
        #pragma unroll
        for (int nt=0; nt<4; nt++){
            int col0 = c0b + nt*8;
            if (col0 < 120){
                float b0 = sb[col0], b1 = sb[col0+1];
                st_af2(hbase, row0, col0,   silu(acc[mt][nt][0]+b0), silu(acc[mt][nt][2]+b0));
                st_af2(hbase, row0, col0+1, silu(acc[mt][nt][1]+b1), silu(acc[mt][nt][3]+b1));
            }
        }
    }
}

// ---------- setup: convert all 10 weights to fragment-layout tf32 ----------
__global__ void conv_weights_kernel(
    const float* __restrict__ w0, const float* __restrict__ w1,
    const float* __restrict__ w2, const float* __restrict__ w3,
    const float* __restrict__ w4, const float* __restrict__ w5,
    const float* __restrict__ w6, const float* __restrict__ w7,
    const float* __restrict__ w8, const float* __restrict__ w9)
{
    int wid = blockIdx.y;
    int l = blockIdx.x*256 + threadIdx.x;
    if (l >= 15360) return;
    const int nktA[10] = {14,3,15,15,15,15,15,15,15,15};
    const int KA[10]   = {112,20,120,120,120,120,120,120,120,120};
    int kt = l>>10;
    if (kt >= nktA[wid]) return;
    const float* W = (wid==0)?w0:(wid==1)?w1:(wid==2)?w2:(wid==3)?w3:(wid==4)?w4:
                     (wid==5)?w5:(wid==6)?w6:(wid==7)?w7:(wid==8)?w8:w9;
    int ld = (wid==9)?112:120;
    int N  = (wid==9)?112:120;
    int K  = KA[wid];
    int rest = l&1023;
    int nti = rest>>6, lane=(rest>>1)&31, r = rest&1;
    int n = nti*8 + (lane>>2);
    int k = kt*8 + (lane&3) + 4*r;
    float v = (n<N && k<K) ? __ldg(W + (size_t)k*ld + n) : 0.f;
    g_wfrag[wid*15360 + l] = f2tf32(v);
}

// ---------- K1: node LayerNorm + O3 LayerNorm + residual copy to out ----------
__global__ void node_norm_kernel(const float* __restrict__ xs_in, const float* __restrict__ xe_in,
                                 const float* __restrict__ lnw, const float* __restrict__ lnb,
                                 const float* __restrict__ o3w, float* __restrict__ out){
    int lane = threadIdx.x & 31;
    int node = blockIdx.x*4 + (threadIdx.x >> 5);
    if (node >= NN) return;
    float* outS = out + (size_t)node*120;
    float* outE = out + (size_t)NN*120 + (size_t)node*240;

    const float* xs = xs_in + (size_t)node*120;
    float v0=xs[lane], v1=xs[lane+32], v2=xs[lane+64], v3=(lane<24)?xs[lane+96]:0.f;
    outS[lane]=v0; outS[lane+32]=v1; outS[lane+64]=v2;
    if (lane<24) outS[lane+96]=v3;
    float s = wsum(v0+v1+v2+v3);
    float q = wsum(v0*v0+v1*v1+v2*v2+v3*v3);
    float mean = s*(1.f/120.f);
    float inv = rsqrtf(q*(1.f/120.f) - mean*mean + 1e-5f);
    float* ns = g_ns + (size_t)node*120;
    ns[lane]    = (v0-mean)*inv*__ldg(lnw+lane)    + __ldg(lnb+lane);
    ns[lane+32] = (v1-mean)*inv*__ldg(lnw+lane+32) + __ldg(lnb+lane+32);
    ns[lane+64] = (v2-mean)*inv*__ldg(lnw+lane+64) + __ldg(lnb+lane+64);
    if (lane<24) ns[lane+96] = (v3-mean)*inv*__ldg(lnw+lane+96) + __ldg(lnb+lane+96);

    const float* xe = xe_in + (size_t)node*240;
    float* ne = g_ne + (size_t)node*240;
    {
        float e0=xe[lane], e1=xe[lane+32];
        outE[lane]=e0; outE[lane+32]=e1;
        float m = wsum(e0+e1)*(1.f/64.f);
        float c0=e0-m, c1=e1-m;
        float r = rsqrtf(wsum(c0*c0+c1*c1)*(1.f/64.f) + 1e-5f);
        ne[lane]    = c0*r*__ldg(o3w+lane);
        ne[lane+32] = c1*r*__ldg(o3w+lane+32);
    }
    {
        float y0=xe[64+lane], y1=xe[96+lane], y2=xe[128+lane];
        outE[64+lane]=y0; outE[96+lane]=y1; outE[128+lane]=y2;
        float r = rsqrtf(wsum(y0*y0+y1*y1+y2*y2)*(1.f/96.f) + 1e-5f);
        ne[64+lane]  = y0*r*__ldg(o3w+64+(lane)/3);
        ne[96+lane]  = y1*r*__ldg(o3w+64+(32+lane)/3);
        ne[128+lane] = y2*r*__ldg(o3w+64+(64+lane)/3);
    }
    {
        float z0=xe[160+lane], z1=xe[192+lane], z2=(lane<16)?xe[224+lane]:0.f;
        outE[160+lane]=z0; outE[192+lane]=z1;
        if (lane<16) outE[224+lane]=z2;
        float r = rsqrtf(wsum(z0*z0+z1*z1+z2*z2)*(1.f/80.f) + 1e-5f);
        ne[160+lane] = z0*r*__ldg(o3w+96+(lane)/5);
        ne[192+lane] = z1*r*__ldg(o3w+96+(32+lane)/5);
        if (lane<16) ne[224+lane] = z2*r*__ldg(o3w+96+(64+lane)/5);
    }
}

// ---------- K2: all 6 projections via mma.sync, A staged once ----------
__global__ __launch_bounds__(256,3) void proj_mma_kernel(void){
    __shared__ alignas(16) float af[15*512];
    int tid = threadIdx.x;
    int warp = tid>>5, lane = tid&31;
    int wm = warp>>2, wn = warp&3;
    int row0 = blockIdx.x * 64;

    for (int idx=tid; idx<64*30; idx+=256){
        int row = idx/30, q = idx - row*30;
        float4 v = ldg4(g_ns + (size_t)(row0+row)*120 + 4*q);
        st_af(af, row, 4*q,   v.x);
        st_af(af, row, 4*q+1, v.y);
        st_af(af, row, 4*q+2, v.z);
        st_af(af, row, 4*q+3, v.w);
    }
    __syncthreads();

    int boff = (wn*4)*64 + lane*2;
    int r0 = wm*32 + (lane>>2);
    int c0b = wn*32 + 2*(lane&3);

    #pragma unroll
    for (int sel=0; sel<6; sel++){
        const u32* bw = g_wfrag + (4+sel)*15360 + boff;
        float* C = (sel==0)?g_qinv:(sel==1)?g_kinv:(sel==2)?g_vinv:(sel==3)?g_qsph:(sel==4)?g_ksph:g_vsph;
        int ncols = (sel==5)?112:120;
        float acc[2][4][4];
        zero_acc(acc);
        #pragma unroll
        for (int kt=0; kt<15; kt++) mma_step(af, bw, kt, wm, lane, acc);
        #pragma unroll
        for (int mt=0; mt<2; mt++){
            int rowA = r0 + mt*16;
            #pragma unroll
            for (int nt=0; nt<4; nt++){
                int col0 = c0b + nt*8;
                if (col0 < ncols){
                    *reinterpret_cast<float2*>(C + (size_t)(row0+rowA)*ncols   + col0) =
                        make_float2(acc[mt][nt][0], acc[mt][nt][1]);
                    *reinterpret_cast<float2*>(C + (size_t)(row0+rowA+8)*ncols + col0) =
                        make_float2(acc[mt][nt][2], acc[mt][nt][3]);
                }
            }
        }
    }
}

// ---------- fused edge kernel: 64-edge tiles, coalesced gather, B frags from L2 ----------
#define AF1X 0
#define AF2X 7680
#define AFRX 15360
#define XSB1 16896
#define XSB2 17024
#define XSB3 17152
#define XFC  17280
#define EM_FLOATS 17344

__global__ __launch_bounds__(256,3) void edge_mma_kernel(
    const int* __restrict__ ei, const float* __restrict__ rbf, const float* __restrict__ fcut,
    const float* __restrict__ inv_b1, const float* __restrict__ inv_b2,
    const float* __restrict__ rbf_b1, const float* __restrict__ rbf_b2)
{
    extern __shared__ float sm[];
    int tid = threadIdx.x;
    int warp = tid>>5, lane = tid&31;
    int wm = warp>>2, wn = warp&3;
    int e0 = blockIdx.x * 64;

    int boff = (wn*4)*64 + lane*2;
    const u32* bw1  = g_wfrag + 0*15360 + boff;
    const u32* bwr1 = g_wfrag + 1*15360 + boff;
    const u32* bw2  = g_wfrag + 2*15360 + boff;
    const u32* bwr2 = g_wfrag + 3*15360 + boff;

    // zero rbf A-frag pad (kt=2, regs 2..3)
    for (int idx=tid; idx<256; idx+=256){
        int mti = idx>>6, rest = idx&63, ln = rest>>1, r = 2+(rest&1);
        sm[AFRX + ((2*4+mti)*32+ln)*4 + r] = 0.f;
    }
    if (tid < 128){
        sm[XSB1+tid] = (tid<120) ? __ldg(inv_b1+tid) : 0.f;
        sm[XSB2+tid] = (tid<120) ? __ldg(rbf_b1+tid) : 0.f;
        sm[XSB3+tid] = (tid<120) ? (__ldg(inv_b2+tid)+__ldg(rbf_b2+tid)) : 0.f;
    }
    if (tid < 64) sm[XFC+tid] = __ldg(fcut + e0 + tid);

    // gather + equi_dot: coalesced float4 loads; l=0 direct from regs; l>=1 via scratch
    {
        float* scr = sm + AF2X + warp*256;
        for (int el = warp; el < 64; el += 8){
            int e = e0 + el;
            int a_n = __ldg(ei+EE+e), b_n = __ldg(ei+e);
            const float* a = g_ne + (size_t)a_n*240;
            const float* b = g_ne + (size_t)b_n*240;
            #pragma unroll
            for (int i=0; i<2; i++){
                int q = lane + 32*i;
                if (q < 60){
                    float4 av = ldg4(a + 4*q), bv = ldg4(b + 4*q);
                    float dx=av.x-bv.x, dy=av.y-bv.y, dz=av.z-bv.z, dw=av.w-bv.w;
                    float4 d2 = make_float4(dx*dx, dy*dy, dz*dz, dw*dw);
                    if (q < 16){
                        st_af(sm+AF1X, el, 4*q,   d2.x);
                        st_af(sm+AF1X, el, 4*q+1, d2.y);
                        st_af(sm+AF1X, el, 4*q+2, d2.z);
                        st_af(sm+AF1X, el, 4*q+3, d2.w);
                    } else {
                        *reinterpret_cast<float4*>(scr + 4*q) = d2;
                    }
                }
            }
            __syncwarp();
            { int bb = 64 + lane*3;
              st_af(sm+AF1X, el, 64+lane, scr[bb]+scr[bb+1]+scr[bb+2]); }
            if (lane<16){ int bb = 160 + lane*5;
              st_af(sm+AF1X, el, 96+lane, scr[bb]+scr[bb+1]+scr[bb+2]+scr[bb+3]+scr[bb+4]); }
            __syncwarp();
        }
    }
    for (int idx=tid; idx<64*20; idx+=256){
        int row = idx/20, k = idx - row*20;
        st_af(sm+AFRX, row, k, __ldg(rbf + (size_t)(e0+row)*20 + k));
    }
    __syncthreads();

    float acc[2][4][4];
    zero_acc(acc);

    // GEMM2: rbf @ rbf_w1
    #pragma unroll
    for (int kt=0; kt<3; kt++) mma_step(sm+AFRX, bwr1, kt, wm, lane, acc);
    __syncthreads();
    epilogue_h(acc, sm+XSB2, sm+AF2X, wm, wn, lane);
    zero_acc(acc);

    // GEMM1: d @ inv_w1
    #pragma unroll
    for (int kt=0; kt<14; kt++) mma_step(sm+AF1X, bw1, kt, wm, lane, acc);
    __syncthreads();
    epilogue_h(acc, sm+XSB1, sm+AF1X, wm, wn, lane);
    zero_acc(acc);
    __syncthreads();

    // GEMM3: h1 @ inv_w2 + h2 @ rbf_w2
    #pragma unroll
    for (int kt=0; kt<15; kt++) mma_step(sm+AF1X, bw2,  kt, wm, lane, acc);
    #pragma unroll
    for (int kt=0; kt<15; kt++) mma_step(sm+AF2X, bwr2, kt, wm, lane, acc);

    // w = (acc + b) * fcut -> g_w
    {
        int r0 = wm*32 + (lane>>2);
        int c0b = wn*32 + 2*(lane&3);
        #pragma unroll
        for (int mt=0; mt<2; mt++){
            int rowA = r0 + mt*16;
            float fA = sm[XFC+rowA], fB = sm[XFC+rowA+8];
            #pragma unroll
            for (int nt=0; nt<4; nt++){
                int col0 = c0b + nt*8;
                if (col0 < 120){
                    float2 va, vb;
                    va.x = (acc[mt][nt][0] + sm[XSB3+col0])  *fA;
                    va.y = (acc[mt][nt][1] + sm[XSB3+col0+1])*fA;
                    vb.x = (acc[mt][nt][2] + sm[XSB3+col0])  *fB;
                    vb.y = (acc[mt][nt][3] + sm[XSB3+col0+1])*fB;
                    *reinterpret_cast<float2*>(g_w + (size_t)(e0+rowA)*120   + col0) = va;
                    *reinterpret_cast<float2*>(g_w + (size_t)(e0+rowA+8)*120 + col0) = vb;
                }
            }
        }
    }
}

// ---------- K6: attention + gated messages + scatter ----------
__global__ __launch_bounds__(256) void edge_attn_kernel(const int* __restrict__ ei,
                                                        const float* __restrict__ fcut,
                                                        const float* __restrict__ rsh,
                                                        float* __restrict__ outS,
                                                        float* __restrict__ outE){
    __shared__ float sgate[8][116];
    int warp = threadIdx.x>>5, lane = threadIdx.x&31;
    int e = blockIdx.x*8 + warp;
    int ct = __ldg(ei+e), nb = __ldg(ei+EE+e);
    float fc = __ldg(fcut+e);
    const float* w  = g_w   + (size_t)e*120;
    const float* qi = g_qinv + (size_t)ct*120;
    const float* ki = g_kinv + (size_t)nb*120;
    const float* vi = g_vinv + (size_t)nb*120;
    const float* qs = g_qsph + (size_t)ct*120;
    const float* ks = g_ksph + (size_t)nb*120;
    const float* vs = g_vsph + (size_t)nb*112;

    float s0=0,s1=0,s2=0,s3=0,t0=0,t1=0,t2=0;
    if (lane < 30){
        float4 wv = ldg4(w + 4*lane);
        float4 q  = ldg4(qi + 4*lane), k = ldg4(ki + 4*lane);
        float4 qe = ldg4(qs + 4*lane), ke = ldg4(ks + 4*lane);
        float wa[4]={wv.x,wv.y,wv.z,wv.w};
        float pa[4]={q.x*k.x, q.y*k.y, q.z*k.z, q.w*k.w};
        float pe[4]={qe.x*ke.x, qe.y*ke.y, qe.z*ke.z, qe.w*ke.w};
        #pragma unroll
        for (int j=0;j<4;j++){
            int idx = 4*lane + j;
            float p = wa[j]*pa[j];
            float pq = wa[j]*pe[j];
            int h = idx/30, l = idx/40;
            s0 += (h==0)?p:0.f; s1 += (h==1)?p:0.f; s2 += (h==2)?p:0.f; s3 += (h==3)?p:0.f;
            t0 += (l==0)?pq:0.f; t1 += (l==1)?pq:0.f; t2 += (l==2)?pq:0.f;
        }
    }
    const float SC_S = 0.091287092917527686f;
    const float SC_E = 0.094491118252306805f;
    s0 = wsum(s0)*SC_S; s1 = wsum(s1)*SC_S; s2 = wsum(s2)*SC_S; s3 = wsum(s3)*SC_S;
    t0 = wsum(t0)*SC_E; t1 = wsum(t1)*SC_E; t2 = wsum(t2)*SC_E;

    if (lane < 30){
        float4 v = ldg4(vi + 4*lane);
        float va[4]={v.x,v.y,v.z,v.w}, m[4];
        #pragma unroll
        for (int j=0;j<4;j++){
            int h = (4*lane+j)/30;
            float ss = (h==0)?s0:((h==1)?s1:((h==2)?s2:s3));
            m[j] = ss*va[j];
        }
        red4(outS + (size_t)ct*120 + 4*lane, m[0],m[1],m[2],m[3]);
    }
    if (lane < 28){
        float4 v = ldg4(vs + 4*lane);
        float va[4]={v.x,v.y,v.z,v.w};
        #pragma unroll
        for (int j=0;j<4;j++){
            int ir = 4*lane + j;
            float tl = (ir<64)?t0:((ir<96)?t1:t2);
            sgate[warp][ir] = tl*va[j]*fc;
        }
    }
    __syncwarp();
    if (lane < 30){
        int base = 8*lane;
        float4 r0 = ldg4(rsh + (size_t)e*240 + base);
        float4 r1 = ldg4(rsh + (size_t)e*240 + base + 4);
        float ra[8]={r0.x,r0.y,r0.z,r0.w,r1.x,r1.y,r1.z,r1.w}, m[8];
        #pragma unroll
        for (int j=0;j<8;j++){
            int c = base + j;
            int ir = (c<64)? c : (c<160)? 64+(c-64)/3 : 96+(c-160)/5;
            m[j] = ra[j]*sgate[warp][ir];
        }
        red4(outE + (size_t)ct*240 + base,     m[0],m[1],m[2],m[3]);
        red4(outE + (size_t)ct*240 + base + 4, m[4],m[5],m[6],m[7]);
    }
}

extern "C" void kernel_launch(void* const* d_in, const int* in_sizes, int n_in,
                              void* d_out, int out_size){
    const float* node_scalar=(const float*)d_in[0];
    const float* node_equi  =(const float*)d_in[1];
    const float* rbf        =(const float*)d_in[2];
    const float* fcut       =(const float*)d_in[3];
    const float* rsh        =(const float*)d_in[4];
    const float* ln_w =(const float*)d_in[5];
    const float* ln_b =(const float*)d_in[6];
    const float* o3w  =(const float*)d_in[7];
    const float* Wq   =(const float*)d_in[8];
    const float* Wk   =(const float*)d_in[9];
    const float* Wv   =(const float*)d_in[10];
    const float* Wqs  =(const float*)d_in[11];
    const float* Wks  =(const float*)d_in[12];
    const float* Wvs  =(const float*)d_in[13];
    const float* rbf_w1=(const float*)d_in[14];
    const float* rbf_b1=(const float*)d_in[15];
    const float* rbf_w2=(const float*)d_in[16];
    const float* rbf_b2=(const float*)d_in[17];
    const float* inv_w1=(const float*)d_in[18];
    const float* inv_b1=(const float*)d_in[19];
    const float* inv_w2=(const float*)d_in[20];
    const float* inv_b2=(const float*)d_in[21];
    const int*   ei    =(const int*)d_in[22];

    float* outS = (float*)d_out;
    float* outE = outS + (size_t)NN*120;

    static cudaStream_t s1 = nullptr;
    static cudaEvent_t evRoot = nullptr, evC = nullptr, evN = nullptr, evP = nullptr;
    if (!s1){
        cudaStreamCreateWithFlags(&s1, cudaStreamNonBlocking);
        cudaEventCreateWithFlags(&evRoot, cudaEventDisableTiming);
        cudaEventCreateWithFlags(&evC, cudaEventDisableTiming);
        cudaEventCreateWithFlags(&evN, cudaEventDisableTiming);
        cudaEventCreateWithFlags(&evP, cudaEventDisableTiming);
        cudaFuncSetAttribute(edge_mma_kernel, cudaFuncAttributeMaxDynamicSharedMemorySize, EM_FLOATS*4);
    }

    // fork s1 from the (possibly capturing) main stream FIRST
    cudaEventRecord(evRoot, (cudaStream_t)0);
    cudaStreamWaitEvent(s1, evRoot, 0);

    // s1: weight conversion (independent of norms)
    conv_weights_kernel<<<dim3(60,10), 256, 0, s1>>>(inv_w1, rbf_w1, inv_w2, rbf_w2,
                                                     Wq, Wk, Wv, Wqs, Wks, Wvs);
    cudaEventRecord(evC, s1);

    // s0: norms (+ residual init)
    node_norm_kernel<<<NN/4, 128>>>(node_scalar, node_equi, ln_w, ln_b, o3w, (float*)d_out);
    cudaEventRecord(evN, (cudaStream_t)0);

    // s1: projections (need norm output + converted weights)
    cudaStreamWaitEvent(s1, evN, 0);
    proj_mma_kernel<<<NN/64, 256, 0, s1>>>();
    cudaEventRecord(evP, s1);

    // s0: edge MLP chain (needs norm [program order] + converted weights [evC])
    cudaStreamWaitEvent((cudaStream_t)0, evC, 0);
    edge_mma_kernel<<<EE/64, 256, EM_FLOATS*4>>>(ei, rbf, fcut, inv_b1, inv_b2, rbf_b1, rbf_b2);

    // s0: attention (needs projections [evP] + edge_mma [program order])
    cudaStreamWaitEvent((cudaStream_t)0, evP, 0);
    edge_attn_kernel<<<EE/8, 256>>>(ei, fcut, rsh, outS, outE);
}